// round 17
// baseline (speedup 1.0000x reference)
#include <cuda_runtime.h>
#include <cuda_fp16.h>
#include <cstdint>

#define GATES 255
#define BM    64
#define NT    256

// Fragment-major fp16 weights, Kc=64 tiles (rebuilt every call, deterministic).
// Per tile (32 KB): offset (ng*4+ks)*2048 + q*512 + lane*16 + reg*4 -> ng-slice
// (8 KB) contiguous at tile_base + ng*8192.
__device__ __half g_gwH[512 * 256];   // 8 tiles
__device__ __half g_zH [256 * 256];   // 4 tiles

// ---- smem layout (bytes), 73728 total -> 3 CTAs/SM ----
// A single buf [64m][64k] fp16 (8 KB) + B single buf (32 KB): serial per-CTA
// pipeline; latency hidden by the 2 co-resident CTAs.
// gates fp16 [64][258] (33024 B) overlays A+B head (disjoint lifetimes).
// leaf_frag (4 A-tiles x 8 KB) separate; phase 3 reads it in place as A.
#define A_OFF      0u
#define B_OFF      8192u                      // ..40960
#define GATES_OFF  0u                         // gates fp16, 33024 B (inside A+B)
#define LEAF_OFF   40960u                     // ..73728
#define SMEM_BYTES 73728u
#define GGLS 258   // halves; 516 B row stride (129 words, odd -> conflict-free)

// named barriers: 1+mg (count 128) for A halves, 3+ng (count 64) for B slices
#define BARN(id, cnt) asm volatile("bar.sync %0, %1;" :: "r"(id), "r"(cnt) : "memory")

__device__ __forceinline__ uint32_t smem_u32(const void* p) {
    uint32_t a;
    asm("{ .reg .u64 t; cvta.to.shared.u64 t, %1; cvt.u32.u64 %0, t; }" : "=r"(a) : "l"(p));
    return a;
}
#define CP_ASYNC16(dst, src) \
    asm volatile("cp.async.cg.shared.global [%0], [%1], 16;" :: "r"(dst), "l"(src) : "memory")
#define CP_COMMIT() asm volatile("cp.async.commit_group;" ::: "memory")
#define CP_WAIT(n)  asm volatile("cp.async.wait_group %0;" :: "n"(n) : "memory")

__device__ __forceinline__ void mma16(float* c, const uint32_t* a, uint32_t b0, uint32_t b1) {
    asm volatile("mma.sync.aligned.m16n8k16.row.col.f32.f16.f16.f32 "
        "{%0,%1,%2,%3}, {%4,%5,%6,%7}, {%8,%9}, {%0,%1,%2,%3};"
        : "+f"(c[0]), "+f"(c[1]), "+f"(c[2]), "+f"(c[3])
        : "r"(a[0]), "r"(a[1]), "r"(a[2]), "r"(a[3]), "r"(b0), "r"(b1));
}
__device__ __forceinline__ float sigmoidf_fast(float v) {
    return __fdividef(1.0f, 1.0f + __expf(-v));
}

// A-frag STS byte addr (Kc=64) for half-quad (row, q), q in 0..15, k0=4q
__device__ __forceinline__ uint32_t afrag_addr(int row, int q) {
    int ra = row >> 4, ks = q >> 2;
    int lane = (row & 7) * 4 + ((2 * q) & 3);
    int reg  = ((row >> 3) & 1) + 2 * ((q >> 1) & 1);
    return (uint32_t)((ra * 4 + ks) * 512 + lane * 16 + reg * 4);
}

// ---- prep kernel (identical math to R14-R16) ----
__global__ void prep_kernel(const float* __restrict__ gw, const float* __restrict__ z) {
    const int t8g = (blockIdx.x * 256 + threadIdx.x) * 8;   // 96 blocks -> 196608 halves
    __half h[8];
    int t8 = (t8g < 131072) ? t8g : (t8g - 131072);
    int lane = (t8 >> 3) & 31;
    int q    = (t8 >> 8) & 3;
    int grp  = (t8 >> 10) & 15;
    int tile = t8 >> 14;
    int ng = grp >> 2, ks = grp & 3;
    int n_base = ng * 64 + (lane >> 2);
    int k_base = tile * 64 + ks * 16 + ((lane & 3) << 1);
    if (t8g < 131072) {
        #pragma unroll
        for (int i = 0; i < 8; i++) {
            int n = n_base + (2 * q + (i >> 2)) * 8;
            int k = k_base + ((i >> 1) & 1) * 8 + (i & 1);
            h[i] = (n < GATES) ? __float2half_rn(gw[k * GATES + n]) : __half(0.0f);
        }
        *(uint4*)&g_gwH[t8] = *(const uint4*)h;
    } else {
        #pragma unroll
        for (int i = 0; i < 8; i++) {
            int n = n_base + (2 * q + (i >> 2)) * 8;
            int k = k_base + ((i >> 1) & 1) * 8 + (i & 1);
            h[i] = __float2half_rn(z[n * 256 + k]);
        }
        *(uint4*)&g_zH[t8] = *(const uint4*)h;
    }
}

// ---- main fused kernel: one CTA = 64 rows, 8 warps (32m x 64n), 3 CTAs/SM ----
extern "C" __global__ void __launch_bounds__(NT, 3)
softtree_h11_kernel(const float* __restrict__ x,
                    const float* __restrict__ gb,
                    float* __restrict__ out)
{
    extern __shared__ char smc[];
    __half* gates = (__half*)(smc + GATES_OFF);
    const uint32_t sb = smem_u32(smc);

    const int tid  = threadIdx.x;
    const int lane = tid & 31;
    const int wid  = tid >> 5;       // 0..7
    const int mg   = wid & 1;        // rows mg*32 .. +31
    const int ng   = wid >> 1;       // cols ng*64 .. +63
    const int g    = lane >> 2;
    const int t4   = lane & 3;
    const int gt   = ng * 32 + lane; // index within mg-group (0..127)
    const int pt   = mg * 32 + lane; // index within ng-pair  (0..63)
    const int rbase = blockIdx.x * BM;

    float acc[2][8][4];
    #pragma unroll
    for (int ra = 0; ra < 2; ra++)
        #pragma unroll
        for (int j = 0; j < 8; j++)
            #pragma unroll
            for (int e = 0; e < 4; e++) acc[ra][j][e] = 0.0f;

    uint32_t xh[8];

    // each ng-pair loads ITS OWN contiguous 8 KB B slice
    auto issueB = [&](const __half* srcTile) {
        const char* s = (const char*)srcTile + (uint32_t)ng * 8192u;
        const uint32_t d = sb + B_OFF + (uint32_t)ng * 8192u;
        #pragma unroll
        for (int j = 0; j < 8; j++) {
            uint32_t off = (uint32_t)(pt + j * 64) * 16u;
            CP_ASYNC16(d + off, s + off);
        }
    };
    // each mg-group stages ITS OWN 32-row A half (rows mg*32 .. +31)
    auto ldgA = [&](int t) {
        #pragma unroll
        for (int j = 0; j < 4; j++) {
            int f = j * 128 + gt;            // 0..511
            int rl = f >> 4, q = f & 15;
            float4 v = *(const float4*)&x[(size_t)(rbase + mg * 32 + rl) * 512 + t * 64 + q * 4];
            __half2 h0 = __floats2half2_rn(v.x, v.y);
            __half2 h1 = __floats2half2_rn(v.z, v.w);
            xh[2 * j]     = *(uint32_t*)&h0;
            xh[2 * j + 1] = *(uint32_t*)&h1;
        }
    };
    auto stsA = [&]() {
        #pragma unroll
        for (int j = 0; j < 4; j++) {
            int f = j * 128 + gt;
            int rl = f >> 4, q = f & 15;
            uint32_t a0 = afrag_addr(mg * 32 + rl, q);
            *(uint32_t*)(smc + A_OFF + a0)      = xh[2 * j];
            *(uint32_t*)(smc + A_OFF + a0 + 16) = xh[2 * j + 1];
        }
    };
    auto compute = [&](uint32_t a_base) {
        #pragma unroll
        for (int ks = 0; ks < 4; ks++) {
            uint32_t a0[4], a1[4];
            *(uint4*)a0 = *(const uint4*)(smc + a_base + (uint32_t)(((mg * 2)     * 4 + ks) * 512 + lane * 16));
            *(uint4*)a1 = *(const uint4*)(smc + a_base + (uint32_t)(((mg * 2 + 1) * 4 + ks) * 512 + lane * 16));
            #pragma unroll
            for (int q = 0; q < 4; q++) {
                uint32_t b[4];
                *(uint4*)b = *(const uint4*)(smc + B_OFF
                              + (uint32_t)((ng * 4 + ks) * 2048 + q * 512 + lane * 16));
                mma16(acc[0][2 * q],     a0, b[0], b[1]);
                mma16(acc[0][2 * q + 1], a0, b[2], b[3]);
                mma16(acc[1][2 * q],     a1, b[0], b[1]);
                mma16(acc[1][2 * q + 1], a1, b[2], b[3]);
            }
        }
    };

    // ============ Phase 1: logits = x @ gwT (8 K-tiles; serial bufs, scoped bars) ============
    ldgA(0);

    #pragma unroll 1
    for (int u = 0; u < 8; u++) {
        if (u > 0) BARN(3 + ng, 64);       // pair done compute(u-1) -> B slice free
        issueB(g_gwH + (size_t)u * 16384);
        CP_COMMIT();
        if (u > 0) BARN(1 + mg, 128);      // group done compute(u-1) -> A half free
        stsA();                            // tile u from xh
        CP_WAIT(0);                        // own B half landed
        BARN(3 + ng, 64);                  // pair's B slice fully visible
        BARN(1 + mg, 128);                 // group's A half fully visible
        compute(A_OFF);
        if (u < 7) ldgA(u + 1);            // xh not live across compute
    }
    __syncthreads();   // all compute(7) retired -> gates region writable

    // ============ bias + sigmoid -> gates (fp16 storage, f32 math; bias from global) ============
    #pragma unroll
    for (int ra = 0; ra < 2; ra++)
        #pragma unroll
        for (int j = 0; j < 8; j++) {
            int row = mg * 32 + ra * 16 + g;
            int col = ng * 64 + j * 8 + 2 * t4;
            float b0 = gb[col];                               // col <= 254 always
            float b1 = (col + 1 < GATES) ? gb[col + 1] : 0.0f;
            *(__half2*)&gates[row * GGLS + col] =
                __floats2half2_rn(sigmoidf_fast(acc[ra][j][0] + b0),
                                  sigmoidf_fast(acc[ra][j][1] + b1));
            *(__half2*)&gates[(row + 8) * GGLS + col] =
                __floats2half2_rn(sigmoidf_fast(acc[ra][j][2] + b0),
                                  sigmoidf_fast(acc[ra][j][3] + b1));
        }
    __syncthreads();   // gates visible to all

    // ============ tree products (f32 math) -> leaf_frag (A-fragment layout, fp16) ============
    {
        const int r = tid & 63;
        const __half* grow = &gates[r * GGLS];
        #pragma unroll
        for (int s = 0; s < 2; s++) {
            const int h8 = (tid >> 6) + 4 * s;   // 0..7, leaves h8*32 .. +31

            float p;
            { float g0 = __half2float(grow[0]);             p = (h8 >> 2) ? 1.0f - g0 : g0; }
            { float g1 = __half2float(grow[1 + (h8 >> 2)]); p = ((h8 >> 1) & 1) ? p - p * g1 : p * g1; }
            { float g2 = __half2float(grow[3 + (h8 >> 1)]); p = (h8 & 1) ? p - p * g2 : p * g2; }
            float Q1[2];
            { float gg = __half2float(grow[7 + h8]); Q1[0] = p * gg; Q1[1] = p - Q1[0]; }
            float Q2[4];
            #pragma unroll
            for (int i = 0; i < 2; i++) {
                float gg = __half2float(grow[15 + 2 * h8 + i]);
                Q2[2 * i] = Q1[i] * gg; Q2[2 * i + 1] = Q1[i] - Q2[2 * i];
            }
            float Q3[8];
            #pragma unroll
            for (int i = 0; i < 4; i++) {
                float gg = __half2float(grow[31 + 4 * h8 + i]);
                Q3[2 * i] = Q2[i] * gg; Q3[2 * i + 1] = Q2[i] - Q3[2 * i];
            }
            const uint32_t tbase = LEAF_OFF + (uint32_t)(h8 >> 1) * 8192u;
            #pragma unroll
            for (int i = 0; i < 8; i++) {
                float gg = __half2float(grow[63 + 8 * h8 + i]);
                float qa = Q3[i] * gg, qb = Q3[i] - qa;
                float g5a = __half2float(grow[127 + 16 * h8 + 2 * i]);
                float v0 = qa * g5a, v1 = qa - v0;
                float g5b = __half2float(grow[127 + 16 * h8 + 2 * i + 1]);
                float v2 = qb * g5b, v3 = qb - v2;
                uint32_t ad = tbase + afrag_addr(r, (h8 & 1) * 8 + i);
                *(__half2*)(smc + ad)      = __floats2half2_rn(v0, v1);
                *(__half2*)(smc + ad + 16) = __floats2half2_rn(v2, v3);
            }
        }
    }
    __syncthreads();   // gates reads retired; leaf_frag complete -> B buf reusable

    // ============ Phase 3: out = leaf @ z^T (4 K-tiles; A in place) ============
    #pragma unroll
    for (int ra = 0; ra < 2; ra++)
        #pragma unroll
        for (int j = 0; j < 8; j++)
            #pragma unroll
            for (int e = 0; e < 4; e++) acc[ra][j][e] = 0.0f;

    #pragma unroll 1
    for (int u = 0; u < 4; u++) {
        if (u > 0) BARN(3 + ng, 64);       // pair done compute(u-1)
        issueB(g_zH + (size_t)u * 16384);
        CP_COMMIT();
        CP_WAIT(0);
        BARN(3 + ng, 64);                  // pair's B slice visible
        compute(LEAF_OFF + (uint32_t)u * 8192u);
    }

    // ============ write out ============
    #pragma unroll
    for (int ra = 0; ra < 2; ra++)
        #pragma unroll
        for (int j = 0; j < 8; j++) {
            int row = rbase + mg * 32 + ra * 16 + g;
            int col = ng * 64 + j * 8 + 2 * t4;
            float2 s0, s1;
            s0.x = acc[ra][j][0]; s0.y = acc[ra][j][1];
            s1.x = acc[ra][j][2]; s1.y = acc[ra][j][3];
            *(float2*)&out[(size_t)row * 256 + col]       = s0;
            *(float2*)&out[(size_t)(row + 8) * 256 + col] = s1;
        }
}

extern "C" void kernel_launch(void* const* d_in, const int* in_sizes, int n_in,
                              void* d_out, int out_size)
{
    const float* x  = (const float*)d_in[0];   // [B, 512]
    const float* gw = (const float*)d_in[1];   // [512, 255]
    const float* gb = (const float*)d_in[2];   // [255]
    const float* z  = (const float*)d_in[3];   // [256, 256]
    float* out = (float*)d_out;                // [B, 256]

    const int B = in_sizes[0] / 512;

    prep_kernel<<<96, 256>>>(gw, z);

    cudaFuncSetAttribute(softtree_h11_kernel,
                         cudaFuncAttributeMaxDynamicSharedMemorySize, SMEM_BYTES);
    softtree_h11_kernel<<<B / BM, NT, SMEM_BYTES>>>(x, gb, out);
}